// round 16
// baseline (speedup 1.0000x reference)
#include <cuda_runtime.h>

#define BB 2
#define CC 128
#define HH 128
#define WW 256
#define KK 20
#define HW (HH * WW)
#define EPSV 1e-12f

typedef unsigned long long u64;

__device__ __forceinline__ u64 pk2(float lo, float hi) {
    u64 r; asm("mov.b64 %0, {%1,%2};" : "=l"(r) : "f"(lo), "f"(hi)); return r;
}
__device__ __forceinline__ void upk2(u64 v, float& lo, float& hi) {
    asm("mov.b64 {%0,%1}, %2;" : "=f"(lo), "=f"(hi) : "l"(v));
}
__device__ __forceinline__ u64 fma2_(u64 a, u64 b, u64 c) {
    u64 d; asm("fma.rn.f32x2 %0, %1, %2, %3;" : "=l"(d) : "l"(a), "l"(b), "l"(c)); return d;
}
__device__ __forceinline__ u64 add2_(u64 a, u64 b) {
    u64 d; asm("add.rn.f32x2 %0, %1, %2;" : "=l"(d) : "l"(a), "l"(b)); return d;
}
__device__ __forceinline__ float wred(float v) {
#pragma unroll
    for (int o = 16; o > 0; o >>= 1) v += __shfl_xor_sync(0xffffffffu, v, o);
    return v;   // full sum present in ALL lanes
}
__device__ __forceinline__ float dot4(float4 a) {
    return a.x * a.x + a.y * a.y + a.z * a.z + a.w * a.w;
}

// Pure 16-c dot chunk: 4-deep LDG prefetch, coalesced x (lane-shared lines),
// padded proto rows -> 2x LDS.128 + 1x LDS.64. NO s2, NO r2 — 10 FFMA2 of
// 13-14 issues per c.
__device__ __forceinline__ void chunk16(const float4* __restrict__ fp, int ccb,
                                        const u64* __restrict__ pb,
                                        u64 acc[2][5]) {
    float4 xb[4];
#pragma unroll
    for (int j = 0; j < 4; j++) xb[j] = fp[(size_t)(ccb + j) * (HW / 4)];

#pragma unroll
    for (int t = 0; t < 16; t++) {
        int cc = ccb + t;
        float4 xv = xb[t & 3];
        if (t < 12) xb[t & 3] = fp[(size_t)(cc + 4) * (HW / 4)];

        u64 x0 = pk2(xv.x, xv.y);
        u64 x1 = pk2(xv.z, xv.w);
        const u64* pr = pb + cc * 24;
        ulonglong2 q0 = *(const ulonglong2*)(pr);
        ulonglong2 q1 = *(const ulonglong2*)(pr + 2);
        u64 p4 = pr[4];
        acc[0][0] = fma2_(x0, q0.x, acc[0][0]);
        acc[1][0] = fma2_(x1, q0.x, acc[1][0]);
        acc[0][1] = fma2_(x0, q0.y, acc[0][1]);
        acc[1][1] = fma2_(x1, q0.y, acc[1][1]);
        acc[0][2] = fma2_(x0, q1.x, acc[0][2]);
        acc[1][2] = fma2_(x1, q1.x, acc[1][2]);
        acc[0][3] = fma2_(x0, q1.y, acc[0][3]);
        acc[1][3] = fma2_(x1, q1.y, acc[1][3]);
        acc[0][4] = fma2_(x0, p4, acc[0][4]);
        acc[1][4] = fma2_(x1, p4, acc[1][4]);
    }
}

// Fused kernel: kg-in-lanes mainloop (r15) + s2 computed in the norms pass.
// Block = (b,h), 512 threads.
// Mainloop tid split: lane = kg*8 + pxl (pxl: 4-px group, kg: 5-k group),
// wh bits5-7 (8 px-warps of 32 px), ch bit8 (c-half of 64).
__global__ __launch_bounds__(512, 2) void iso_kernel(const float* __restrict__ f,
                                                     const float* __restrict__ p,
                                                     const float* __restrict__ ds,
                                                     float* __restrict__ out) {
    __shared__ u64 s_pn[CC * 24];      // padded folded protos (24 KB); aliased s_red after
    __shared__ float s_s2part[16 * 256]; // per-warp s2 partials (16 KB)
    __shared__ float s_s2f[256];       // final ||fn||^2 per pixel (1 KB)
    __shared__ float s_inv[CC];
    __shared__ float s_pinv[KK];
    __shared__ float s_pn2[KK];

    int tid = threadIdx.x;
    int w = tid >> 5, lane = tid & 31;
    int b = blockIdx.x / HH, h = blockIdx.x % HH;
    const float* fbh = f + (size_t)b * CC * HW + (size_t)h * WW;

    // ---- Pass 1a: W-norms AND per-pixel s2 partials.
    // Warp w handles c = w + 16j (8 c). Lane holds x for w-positions
    // 4*lane..4*lane+3 (v even) and 128+4*lane.. (v odd); accumulates x^2*r^2.
    float4 a0 = make_float4(0.f, 0.f, 0.f, 0.f);
    float4 a1 = make_float4(0.f, 0.f, 0.f, 0.f);
#pragma unroll
    for (int jb = 0; jb < 2; jb++) {
        float4 v[8];
        int cbase = w + jb * 64;
#pragma unroll
        for (int j = 0; j < 4; j++) {
            const float4* r4 = (const float4*)(fbh + (size_t)(cbase + 16 * j) * HW);
            v[2 * j]     = r4[lane];
            v[2 * j + 1] = r4[lane + 32];
        }
#pragma unroll
        for (int j = 0; j < 4; j++) {
            float s = wred(dot4(v[2 * j]) + dot4(v[2 * j + 1]));   // sum in all lanes
            float r = 1.0f / fmaxf(sqrtf(s), EPSV);
            if (lane == 0) s_inv[cbase + 16 * j] = r;
            float r2 = r * r;
            float4 e = v[2 * j], o = v[2 * j + 1];
            a0.x = fmaf(e.x * e.x, r2, a0.x);
            a0.y = fmaf(e.y * e.y, r2, a0.y);
            a0.z = fmaf(e.z * e.z, r2, a0.z);
            a0.w = fmaf(e.w * e.w, r2, a0.w);
            a1.x = fmaf(o.x * o.x, r2, a1.x);
            a1.y = fmaf(o.y * o.y, r2, a1.y);
            a1.z = fmaf(o.z * o.z, r2, a1.z);
            a1.w = fmaf(o.w * o.w, r2, a1.w);
        }
    }
    *(float4*)(s_s2part + w * 256 + lane * 4)       = a0;
    *(float4*)(s_s2part + w * 256 + 128 + lane * 4) = a1;

    // ---- Pass 1b: prototype norms
    for (int k = w; k < KK; k += 16) {
        float4 a = ((const float4*)(p + k * CC))[lane];
        float s = wred(dot4(a));
        if (lane == 0) {
            float inv = 1.0f / fmaxf(sqrtf(s), EPSV);
            s_pinv[k] = inv;
            s_pn2[k] = s * inv * inv;
        }
    }
    __syncthreads();

    // ---- s2 final reduction (256 threads) + folded proto table (all threads)
    if (tid < 256) {
        float t = 0.0f;
#pragma unroll
        for (int g = 0; g < 16; g++) t += s_s2part[g * 256 + tid];
        s_s2f[tid] = t;
    }
    for (int i = tid; i < CC * KK; i += 512) {
        int c = i / KK, k = i - c * KK;
        int kg_ = k / 5, j = k - kg_ * 5;
        float val = __ldg(p + k * CC + c) * s_pinv[k] * s_inv[c];
        s_pn[(c * 4 + kg_) * 6 + j] = pk2(val, val);
    }
    __syncthreads();

    // ---- Main dot loop (kg-in-lanes, pure)
    int pxl = lane & 7;
    int kg = lane >> 3;
    int wh = (tid >> 5) & 7;
    int ch = tid >> 8;
    int c0 = ch * 64;

    const float4* fp = (const float4*)fbh + (size_t)c0 * (HW / 4) + wh * 8 + pxl;
    const u64* pb = s_pn + (size_t)(c0 * 4 + kg) * 6;

    u64 acc[2][5];
#pragma unroll
    for (int j = 0; j < 5; j++) { acc[0][j] = 0ull; acc[1][j] = 0ull; }

#pragma unroll
    for (int seg = 0; seg < 4; seg++)
        chunk16(fp, seg * 16, pb, acc);

    // ---- Cross-ch reduction (alias dead s_pn)
    __syncthreads();                 // all threads done reading s_pn
    u64* s_red = s_pn;               // ch1 dot partials: [256 slots][10]
    if (ch == 1) {
        u64* r = s_red + (size_t)(tid & 255) * 10;
#pragma unroll
        for (int i = 0; i < 2; i++)
#pragma unroll
            for (int j = 0; j < 5; j++) r[i * 5 + j] = acc[i][j];
    }
    __syncthreads();

    if (ch == 0) {
        const u64* r = s_red + (size_t)tid * 10;
#pragma unroll
        for (int i = 0; i < 2; i++)
#pragma unroll
            for (int j = 0; j < 5; j++) acc[i][j] = add2_(acc[i][j], r[i * 5 + j]);

        float4 nn = *(const float4*)(s_s2f + wh * 32 + pxl * 4);

        float scale = fabsf(ds[0]);
        float* ob = out + (size_t)b * KK * HW + (size_t)h * WW + wh * 32 + pxl * 4;
#pragma unroll
        for (int j = 0; j < 5; j++) {
            int k = kg * 5 + j;
            float q = s_pn2[k];
            float d0, d1, d2, d3;
            upk2(acc[0][j], d0, d1);
            upk2(acc[1][j], d2, d3);
            float4 o;
            o.x = -scale * sqrtf(fmaxf(nn.x + q - 2.0f * d0, 0.0f));
            o.y = -scale * sqrtf(fmaxf(nn.y + q - 2.0f * d1, 0.0f));
            o.z = -scale * sqrtf(fmaxf(nn.z + q - 2.0f * d2, 0.0f));
            o.w = -scale * sqrtf(fmaxf(nn.w + q - 2.0f * d3, 0.0f));
            *(float4*)(ob + (size_t)k * HW) = o;
        }
    }
}

extern "C" void kernel_launch(void* const* d_in, const int* in_sizes, int n_in,
                              void* d_out, int out_size) {
    const float* features   = (const float*)d_in[0];
    const float* prototypes = (const float*)d_in[1];
    const float* dscale     = (const float*)d_in[2];
    float* out = (float*)d_out;

    iso_kernel<<<BB * HH, 512>>>(features, prototypes, dscale, out);
}

// round 17
// speedup vs baseline: 1.0989x; 1.0989x over previous
#include <cuda_runtime.h>

#define BB 2
#define CC 128
#define HH 128
#define WW 256
#define KK 20
#define HW (HH * WW)
#define EPSV 1e-12f

typedef unsigned long long u64;

__device__ __forceinline__ u64 pk2(float lo, float hi) {
    u64 r; asm("mov.b64 %0, {%1,%2};" : "=l"(r) : "f"(lo), "f"(hi)); return r;
}
__device__ __forceinline__ void upk2(u64 v, float& lo, float& hi) {
    asm("mov.b64 {%0,%1}, %2;" : "=f"(lo), "=f"(hi) : "l"(v));
}
__device__ __forceinline__ u64 fma2_(u64 a, u64 b, u64 c) {
    u64 d; asm("fma.rn.f32x2 %0, %1, %2, %3;" : "=l"(d) : "l"(a), "l"(b), "l"(c)); return d;
}
__device__ __forceinline__ u64 mul2_(u64 a, u64 b) {
    u64 d; asm("mul.rn.f32x2 %0, %1, %2;" : "=l"(d) : "l"(a), "l"(b)); return d;
}
__device__ __forceinline__ u64 add2_(u64 a, u64 b) {
    u64 d; asm("add.rn.f32x2 %0, %1, %2;" : "=l"(d) : "l"(a), "l"(b)); return d;
}
__device__ __forceinline__ float wred(float v) {
#pragma unroll
    for (int o = 16; o > 0; o >>= 1) v += __shfl_xor_sync(0xffffffffu, v, o);
    return v;
}
__device__ __forceinline__ float dot4(float4 a) {
    return a.x * a.x + a.y * a.y + a.z * a.z + a.w * a.w;
}

// 16-c chunk with 4-deep LDG prefetch pipeline (r10 champion, unchanged).
template <bool DO_S2>
__device__ __forceinline__ void chunk16(const float4* __restrict__ fp, int ccb,
                                        const u64* __restrict__ pb,     // s_pn + (c0*4+kg)*6
                                        const u64* __restrict__ r2b,    // s_r2 + c0
                                        u64 acc[2][5], u64 s2[2]) {
    float4 xb[4];
#pragma unroll
    for (int j = 0; j < 4; j++) xb[j] = fp[(size_t)(ccb + j) * (HW / 4)];

#pragma unroll
    for (int t = 0; t < 16; t++) {
        int cc = ccb + t;
        float4 xv = xb[t & 3];
        if (t < 12) xb[t & 3] = fp[(size_t)(cc + 4) * (HW / 4)];

        u64 x0 = pk2(xv.x, xv.y);
        u64 x1 = pk2(xv.z, xv.w);
        const u64* pr = pb + cc * 24;
        ulonglong2 q0 = *(const ulonglong2*)(pr);
        ulonglong2 q1 = *(const ulonglong2*)(pr + 2);
        u64 p4 = pr[4];
        acc[0][0] = fma2_(x0, q0.x, acc[0][0]);
        acc[1][0] = fma2_(x1, q0.x, acc[1][0]);
        acc[0][1] = fma2_(x0, q0.y, acc[0][1]);
        acc[1][1] = fma2_(x1, q0.y, acc[1][1]);
        acc[0][2] = fma2_(x0, q1.x, acc[0][2]);
        acc[1][2] = fma2_(x1, q1.x, acc[1][2]);
        acc[0][3] = fma2_(x0, q1.y, acc[0][3]);
        acc[1][3] = fma2_(x1, q1.y, acc[1][3]);
        acc[0][4] = fma2_(x0, p4, acc[0][4]);
        acc[1][4] = fma2_(x1, p4, acc[1][4]);
        if (DO_S2) {
            u64 r2 = r2b[cc];
            s2[0] = fma2_(mul2_(x0, r2), x0, s2[0]);
            s2[1] = fma2_(mul2_(x1, r2), x1, s2[1]);
        }
    }
}

// Fused kernel (r10 structure + symmetric pair-split tail). Block = (b,h), 512 thr.
// tid: pxg bits0-5 (64 x 4 px), kg bits6-7 (4 x 5 k), ch bit8 (c-half).
// Tail: each thread keeps the pixel PAIR equal to its ch (pair0 = px 4pxg..+1,
// pair1 = px 4pxg+2..+3), exchanges the other pair via SMEM, and writes
// 5 k x 2 px -> all 512 threads work in the tail.
__global__ __launch_bounds__(512, 2) void iso_kernel(const float* __restrict__ f,
                                                     const float* __restrict__ p,
                                                     const float* __restrict__ ds,
                                                     float* __restrict__ out) {
    __shared__ u64 s_pn[CC * 24];    // padded folded protos (24 KB); aliased for tail exchange
    __shared__ u64 s_s2p[8 * 128];   // s2 partials per (ch*4+kg) group (8 KB)
    __shared__ u64 s_r2[CC];         // inv_c^2 dup-packed
    __shared__ float s_inv[CC];
    __shared__ float s_pinv[KK];
    __shared__ float s_pn2[KK];

    int tid = threadIdx.x;
    int w = tid >> 5, lane = tid & 31;
    int b = blockIdx.x / HH, h = blockIdx.x % HH;
    const float* fbh = f + (size_t)b * CC * HW + (size_t)h * WW;

    // ---- Pass 1a: W-norms; warp w handles c = w + 16j (8 c/warp, 4-row batches)
#pragma unroll
    for (int jb = 0; jb < 2; jb++) {
        float4 v[8];
        int cbase = w + jb * 64;
#pragma unroll
        for (int j = 0; j < 4; j++) {
            const float4* r4 = (const float4*)(fbh + (size_t)(cbase + 16 * j) * HW);
            v[2 * j]     = r4[lane];
            v[2 * j + 1] = r4[lane + 32];
        }
#pragma unroll
        for (int j = 0; j < 4; j++) {
            float s = wred(dot4(v[2 * j]) + dot4(v[2 * j + 1]));
            if (lane == 0) {
                int c = cbase + 16 * j;
                float r = 1.0f / fmaxf(sqrtf(s), EPSV);
                s_inv[c] = r;
                s_r2[c] = pk2(r * r, r * r);
            }
        }
    }
    // ---- Pass 1b: prototype norms
    for (int k = w; k < KK; k += 16) {
        float4 a = ((const float4*)(p + k * CC))[lane];
        float s = wred(dot4(a));
        if (lane == 0) {
            float inv = 1.0f / fmaxf(sqrtf(s), EPSV);
            s_pinv[k] = inv;
            s_pn2[k] = s * inv * inv;
        }
    }
    __syncthreads();

    // ---- Folded prototype table, padded layout: s_pn[(c*4+kg)*6+j]
    for (int i = tid; i < CC * KK; i += 512) {
        int c = i / KK, k = i - c * KK;
        int kg_ = k / 5, j = k - kg_ * 5;
        float val = __ldg(p + k * CC + c) * s_pinv[k] * s_inv[c];
        s_pn[(c * 4 + kg_) * 6 + j] = pk2(val, val);
    }
    __syncthreads();

    // ---- Main dot loop (unchanged from r10 champion)
    int pxg = tid & 63;
    int kg = (tid >> 6) & 3;
    int ch = tid >> 8;
    int c0 = ch * 64;

    const float4* fp = (const float4*)fbh + (size_t)c0 * (HW / 4) + pxg;
    const u64* pb = s_pn + (size_t)(c0 * 4 + kg) * 6;
    const u64* r2b = s_r2 + c0;

    u64 acc[2][5];
#pragma unroll
    for (int j = 0; j < 5; j++) { acc[0][j] = 0ull; acc[1][j] = 0ull; }
    u64 s2[2] = {0ull, 0ull};

#pragma unroll
    for (int seg = 0; seg < 4; seg++) {
        if (seg == kg) chunk16<true>(fp, seg * 16, pb, r2b, acc, s2);
        else           chunk16<false>(fp, seg * 16, pb, r2b, acc, s2);
    }

    // ---- Tail: symmetric pair-split reduction + epilogue.
    // s2 partials (both pairs) to SMEM as before.
    s_s2p[(size_t)(ch * 4 + kg) * 128 + 2 * pxg]     = s2[0];
    s_s2p[(size_t)(ch * 4 + kg) * 128 + 2 * pxg + 1] = s2[1];
    __syncthreads();            // all threads done reading s_pn

    // Exchange the non-owned pair: region[pair] collects that pair's partials
    // from the OTHER half. slot = tid&255 is the (pxg,kg) key shared by partners.
    u64* s_red = s_pn;          // region0: [0,1280) u64 ; region1: [1280,2560)
    int slot = tid & 255;
    {
        int otherPair = 1 - ch;
        u64* wr = s_red + (size_t)otherPair * 1280 + (size_t)slot * 5;
#pragma unroll
        for (int j = 0; j < 5; j++) wr[j] = acc[otherPair][j];
    }
    __syncthreads();

    // Each thread finalizes its own pair (index = ch).
    {
        int pair = ch;
        const u64* r = s_red + (size_t)pair * 1280 + (size_t)slot * 5;
        u64 fin[5];
#pragma unroll
        for (int j = 0; j < 5; j++) fin[j] = add2_(acc[pair][j], r[j]);

        // 8-way s2 sum for this pair only
        u64 t = 0ull;
#pragma unroll
        for (int g = 0; g < 8; g++) t = add2_(t, s_s2p[g * 128 + 2 * pxg + pair]);
        float n0, n1;
        upk2(t, n0, n1);

        float scale = fabsf(ds[0]);
        float* ob = out + (size_t)b * KK * HW + (size_t)h * WW + 4 * pxg + 2 * pair;
#pragma unroll
        for (int j = 0; j < 5; j++) {
            int k = kg * 5 + j;
            float q = s_pn2[k];
            float d0, d1;
            upk2(fin[j], d0, d1);
            float2 o;
            o.x = -scale * sqrtf(fmaxf(n0 + q - 2.0f * d0, 0.0f));
            o.y = -scale * sqrtf(fmaxf(n1 + q - 2.0f * d1, 0.0f));
            *(float2*)(ob + (size_t)k * HW) = o;
        }
    }
}

extern "C" void kernel_launch(void* const* d_in, const int* in_sizes, int n_in,
                              void* d_out, int out_size) {
    const float* features   = (const float*)d_in[0];
    const float* prototypes = (const float*)d_in[1];
    const float* dscale     = (const float*)d_in[2];
    float* out = (float*)d_out;

    iso_kernel<<<BB * HH, 512>>>(features, prototypes, dscale, out);
}